// round 11
// baseline (speedup 1.0000x reference)
#include <cuda_runtime.h>
#include <cuda_bf16.h>
#include <cuda_fp16.h>
#include <cstdint>

#define NN 50000
#define EE 800000
#define RR 4
#define GG 16

// ---------------- scratch (device globals; no allocation) ----------------
__device__ __half  g_Ysh[NN * 128];         // self+bias fp16 [N][out]
__device__ __half  g_Ym[NN * 512];          // messages fp16 [N][4*out] (L2-resident)
__device__ __half  g_Asp[NN * 128];         // activations fp16 [N][128]
__device__ __half  g_Bsp[128 * 640];        // weights fp16, row-major [k][5*out]
__device__ float   g_q[GG * 64];
__device__ int     g_cnt[RR * NN];          // ALWAYS zero at call entry (scan1 re-zeroes)
__device__ float   g_inv[NN * 4];
__device__ int     g_deg[NN];
__device__ int     g_part[256];
__device__ int     g_rowptr[NN + 1];
__device__ int     g_fill[NN];
__device__ int     g_csr[EE];               // src | (rel<<28)

// ---------------- host-side stream/event for capture fork-join ----------------
struct HxStreams {
    cudaStream_t s2;
    cudaEvent_t evA, evB;
    HxStreams() {
        cudaStreamCreateWithFlags(&s2, cudaStreamNonBlocking);
        cudaEventCreateWithFlags(&evA, cudaEventDisableTiming);
        cudaEventCreateWithFlags(&evB, cudaEventDisableTiming);
    }
};
static HxStreams g_hx;

// ---------------- helpers ----------------
__device__ __forceinline__ uint32_t smem_u32(const void* p) {
    return (uint32_t)__cvta_generic_to_shared(p);
}
__device__ __forceinline__ void ldsm4(uint32_t* d, const __half* p) {
    uint32_t a = smem_u32(p);
    asm volatile("ldmatrix.sync.aligned.m8n8.x4.shared.b16 {%0,%1,%2,%3}, [%4];"
                 : "=r"(d[0]), "=r"(d[1]), "=r"(d[2]), "=r"(d[3]) : "r"(a));
}
__device__ __forceinline__ void ldsm4t(uint32_t* d, const __half* p) {
    uint32_t a = smem_u32(p);
    asm volatile("ldmatrix.sync.aligned.m8n8.x4.trans.shared.b16 {%0,%1,%2,%3}, [%4];"
                 : "=r"(d[0]), "=r"(d[1]), "=r"(d[2]), "=r"(d[3]) : "r"(a));
}
__device__ __forceinline__ void mma16816(float* c, const uint32_t* a, uint32_t b0, uint32_t b1) {
    asm volatile(
        "mma.sync.aligned.m16n8k16.row.col.f32.f16.f16.f32 "
        "{%0,%1,%2,%3}, {%4,%5,%6,%7}, {%8,%9}, {%0,%1,%2,%3};"
        : "+f"(c[0]), "+f"(c[1]), "+f"(c[2]), "+f"(c[3])
        : "r"(a[0]), "r"(a[1]), "r"(a[2]), "r"(a[3]), "r"(b0), "r"(b1));
}
__device__ __forceinline__ void cp_async16(uint32_t smem_addr, const void* gptr) {
    asm volatile("cp.async.cg.shared.global [%0], [%1], 16;" :: "r"(smem_addr), "l"(gptr));
}
__device__ __forceinline__ void cp_commit() {
    asm volatile("cp.async.commit_group;" ::: "memory");
}
template <int N>
__device__ __forceinline__ void cp_wait() {
    asm volatile("cp.async.wait_group %0;" :: "n"(N) : "memory");
}
__device__ __forceinline__ float pick4(float4 v, int r) {
    return r == 0 ? v.x : (r == 1 ? v.y : (r == 2 ? v.z : v.w));
}

// ---------------- prepB body ----------------
__device__ __forceinline__ void prepB_body(int idx, const float* __restrict__ root,
                                           const float* __restrict__ W, int out) {
    int ncols = 5 * out;
    if (idx >= 128 * ncols) return;
    int k = idx / ncols, j = idx % ncols;
    float v = (j < out) ? root[k * out + j]
                        : W[((j / out - 1) * 128 + k) * out + (j % out)];
    g_Bsp[idx] = __float2half_rn(v);
}

// ---------------- mega1: prepA0 + edge count + prepB0 + q projection ----------------
#define PA_BLK 25000
#define CNT_BLK 3125
#define PB0_BLK 160
#define Q_BLK 16
__global__ void __launch_bounds__(256) k_mega1(
    const float* __restrict__ x, const int* __restrict__ dst, const int* __restrict__ ea,
    const float* __restrict__ root0, const float* __restrict__ W0,
    const float* __restrict__ qe, const float* __restrict__ qnW, const float* __restrict__ qnb) {
    int b = blockIdx.x, t = threadIdx.x;
    if (b < PA_BLK) {
        int idx = b * 256 + t;
        g_Asp[idx] = __float2half_rn(x[idx]);
    } else if (b < PA_BLK + CNT_BLK) {
        int e = (b - PA_BLK) * 256 + t;
        atomicAdd(&g_cnt[ea[e] * NN + dst[e]], 1);
    } else if (b < PA_BLK + CNT_BLK + PB0_BLK) {
        prepB_body((b - PA_BLK - CNT_BLK) * 256 + t, root0, W0, 64);
    } else {
        __shared__ float sq[768];
        int g = b - PA_BLK - CNT_BLK - PB0_BLK;
        for (int i = t; i < 768; i += 256) sq[i] = qe[g * 768 + i];
        __syncthreads();
        if (t < 64) {
            float acc = qnb[t];
            for (int k = 0; k < 768; k++) acc = fmaf(sq[k], qnW[k * 64 + t], acc);
            g_q[g * 64 + t] = fmaxf(acc, 0.0f);
        }
    }
}

// ---------------- CSR scans (scan1 re-zeroes g_cnt) ----------------
__global__ void k_scan1() {
    int t = threadIdx.x;
    int i = blockIdx.x * 256 + t;
    int tot = 0;
    if (i < NN) {
#pragma unroll
        for (int r = 0; r < RR; r++) {
            int c = g_cnt[r * NN + i];
            g_cnt[r * NN + i] = 0;
            tot += c;
            g_inv[i * 4 + r] = 1.0f / (float)max(c, 1);
        }
        g_deg[i] = tot;
    }
    __shared__ int s[256];
    s[t] = tot;
    __syncthreads();
    for (int d = 128; d; d >>= 1) {
        if (t < d) s[t] += s[t + d];
        __syncthreads();
    }
    if (t == 0) g_part[blockIdx.x] = s[0];
}
// merged scan2+scan3: each block scans partials redundantly, then its node range
__global__ void k_scan23() {
    int t = threadIdx.x;
    int bid = blockIdx.x;
    __shared__ int sp[256];
    int pv = (t < 196) ? g_part[t] : 0;
    sp[t] = pv;
    __syncthreads();
    for (int d = 1; d < 256; d <<= 1) {
        int x = (t >= d) ? sp[t - d] : 0;
        __syncthreads();
        sp[t] += x;
        __syncthreads();
    }
    int base = (bid == 0) ? 0 : sp[bid - 1];
    int total = sp[195];
    __shared__ int s[256];
    int i = bid * 256 + t;
    int v = (i < NN) ? g_deg[i] : 0;
    s[t] = v;
    __syncthreads();
    for (int d = 1; d < 256; d <<= 1) {
        int x = (t >= d) ? s[t - d] : 0;
        __syncthreads();
        s[t] += x;
        __syncthreads();
    }
    if (i < NN) {
        int off = base + s[t] - v;
        g_rowptr[i] = off;
        g_fill[i] = off;
    }
    if (bid == 195 && t == 0) g_rowptr[NN] = total;
}
__global__ void k_fill(const int* __restrict__ src, const int* __restrict__ dst,
                       const int* __restrict__ ea) {
    int e = blockIdx.x * blockDim.x + threadIdx.x;
    if (e >= EE) return;
    int d = dst[e];
    int pos = atomicAdd(&g_fill[d], 1);
    g_csr[pos] = src[e] | (ea[e] << 28);
}

// ---------------- GEMM: 64-row CTAs, 64-col iters, 6 CTA/SM ----------------
#define AST 136
#define BSTn 72
#define GEMM_SMEM ((64 * AST + 128 * BSTn) * 2)

__global__ void __launch_bounds__(128, 6) k_gemm(const float* __restrict__ bias,
                                                 int out, int niter) {
    extern __shared__ __half smem[];
    __half* sA = smem;                 // [64][AST]
    __half* sB = smem + 64 * AST;      // [128][BSTn]
    int m0 = blockIdx.x * 64;
    int t = threadIdx.x;
    int ncols = 5 * out;

#pragma unroll
    for (int i = 0; i < 8; i++) {
        int idx = t + i * 128;
        int row = idx >> 4;
        int c8 = (idx & 15) * 8;
        int grow = m0 + row;
        uint4 val = make_uint4(0, 0, 0, 0);
        if (grow < NN) val = *(const uint4*)(g_Asp + (size_t)grow * 128 + c8);
        *(uint4*)(sA + row * AST + c8) = val;
    }

    int w = t >> 5, lane = t & 31;
    int wm = (w & 1) * 32, wn = (w >> 1) * 32;
    int lr = lane & 15, lc = lane >> 4;
    int g = lane >> 2, tg = lane & 3;
    int pitchM = 4 * out;

    for (int nb = 0; nb < niter; nb++) {
        int n0 = nb * 64;
        __syncthreads();
        {
            uint32_t sbb = smem_u32(sB);
#pragma unroll
            for (int i = 0; i < 8; i++) {
                int idx = t + i * 128;
                int row = idx >> 3;
                int c8 = (idx & 7) * 8;
                cp_async16(sbb + (row * BSTn + c8) * 2, g_Bsp + (size_t)row * ncols + n0 + c8);
            }
            cp_commit();
            cp_wait<0>();
        }
        __syncthreads();

        float acc[2][4][4];
#pragma unroll
        for (int mt = 0; mt < 2; mt++)
#pragma unroll
            for (int nt = 0; nt < 4; nt++)
#pragma unroll
                for (int i = 0; i < 4; i++) acc[mt][nt][i] = 0.0f;

#pragma unroll
        for (int kk = 0; kk < 8; kk++) {
            uint32_t b[2][4];
#pragma unroll
            for (int nh = 0; nh < 2; nh++)
                ldsm4t(b[nh], sB + (kk * 16 + lr) * BSTn + wn + nh * 16 + lc * 8);
            uint32_t a[2][4];
#pragma unroll
            for (int mt = 0; mt < 2; mt++)
                ldsm4(a[mt], sA + (wm + mt * 16 + lr) * AST + kk * 16 + lc * 8);
#pragma unroll
            for (int mt = 0; mt < 2; mt++)
#pragma unroll
                for (int nt = 0; nt < 4; nt++) {
                    int nh = nt >> 1, h = (nt & 1) * 2;
                    mma16816(acc[mt][nt], a[mt], b[nh][h], b[nh][h + 1]);
                }
        }

#pragma unroll
        for (int mt = 0; mt < 2; mt++) {
#pragma unroll
            for (int nt = 0; nt < 4; nt++) {
                int col = n0 + wn + nt * 8 + tg * 2;
                int r0 = m0 + wm + mt * 16 + g;
                int r1 = r0 + 8;
                if (col < out) {
                    float b0 = bias[col], b1 = bias[col + 1];
                    if (r0 < NN)
                        *(__half2*)(g_Ysh + (size_t)r0 * out + col) =
                            __floats2half2_rn(acc[mt][nt][0] + b0, acc[mt][nt][1] + b1);
                    if (r1 < NN)
                        *(__half2*)(g_Ysh + (size_t)r1 * out + col) =
                            __floats2half2_rn(acc[mt][nt][2] + b0, acc[mt][nt][3] + b1);
                } else {
                    int mc = col - out;
                    if (r0 < NN)
                        *(__half2*)(g_Ym + (size_t)r0 * pitchM + mc) =
                            __floats2half2_rn(acc[mt][nt][0], acc[mt][nt][1]);
                    if (r1 < NN)
                        *(__half2*)(g_Ym + (size_t)r1 * pitchM + mc) =
                            __floats2half2_rn(acc[mt][nt][2], acc[mt][nt][3]);
                }
            }
        }
    }
}

// ---------------- aggregation: WPN warps/node, V=2 cols-per-lane ----------------
// MODE 0: relu(total) fp16 -> g_Asp ; MODE 1: total fp32 -> Optr
template <int OUT, int MODE, int QF, int NXT, int WPN>
__global__ void __launch_bounds__(256) k_agg(float* __restrict__ Optr,
                                             const int* __restrict__ batch,
                                             const float* __restrict__ root,
                                             const float* __restrict__ W) {
    constexpr int AGGB = (NN * WPN * 32 + 255) / 256;
    if (NXT > 0 && blockIdx.x >= AGGB) {
        prepB_body((blockIdx.x - AGGB) * 256 + threadIdx.x, root, W, NXT);
        return;
    }
    int gw = (blockIdx.x * 256 + threadIdx.x) >> 5;
    int w = (WPN == 2) ? (gw >> 1) : gw;
    int colbase = (WPN == 2) ? (gw & 1) * 64 : 0;
    if (w >= NN) return;
    int lane = threadIdx.x & 31;
    constexpr int PITCH = 4 * OUT;
    int start = g_rowptr[w], end = g_rowptr[w + 1];
    float4 iv4 = *(const float4*)(g_inv + w * 4);
    int co = colbase + lane * 2;

    float acc0, acc1;
    {
        uint32_t s = *(const uint32_t*)(g_Ysh + (size_t)w * OUT + co);
        float2 s0 = __half22float2(*(__half2*)&s);
        acc0 = s0.x; acc1 = s0.y;
    }

    int e = start;
    for (; e + 8 <= end; e += 8) {
        int u[8];
#pragma unroll
        for (int j = 0; j < 8; j++) u[j] = g_csr[e + j];
        const __half* p[8];
        float iv[8];
#pragma unroll
        for (int j = 0; j < 8; j++) {
            int s = u[j] & 0x0FFFFFFF;
            int r = ((unsigned)u[j]) >> 28;
            p[j] = g_Ym + (size_t)s * PITCH + r * OUT + co;
            iv[j] = pick4(iv4, r);
        }
        uint32_t d[8];
#pragma unroll
        for (int j = 0; j < 8; j++) d[j] = *(const uint32_t*)p[j];
#pragma unroll
        for (int j = 0; j < 8; j++) {
            float2 m0 = __half22float2(*(__half2*)&d[j]);
            acc0 += m0.x * iv[j]; acc1 += m0.y * iv[j];
        }
    }
    for (; e < end; e++) {
        int u0 = g_csr[e];
        int s0 = u0 & 0x0FFFFFFF, r0 = ((unsigned)u0) >> 28;
        uint32_t d0 = *(const uint32_t*)(g_Ym + (size_t)s0 * PITCH + r0 * OUT + co);
        float i0 = pick4(iv4, r0);
        float2 m0 = __half22float2(*(__half2*)&d0);
        acc0 += m0.x * i0; acc1 += m0.y * i0;
    }

    if constexpr (MODE == 0) {
        __half2 ph = __floats2half2_rn(fmaxf(acc0, 0.0f), fmaxf(acc1, 0.0f));
        *(__half2*)(g_Asp + (size_t)w * 128 + co) = ph;
        if constexpr (QF) {
            int b = batch[w];
            __half2 hh;
            hh.x = __float2half_rn(g_q[b * 64 + lane * 2]);
            hh.y = __float2half_rn(g_q[b * 64 + lane * 2 + 1]);
            *(__half2*)(g_Asp + (size_t)w * 128 + 64 + lane * 2) = hh;
        }
    } else {
        float2 r; r.x = acc0; r.y = acc1;
        *(float2*)(Optr + (size_t)w * OUT + co) = r;
    }
}

// ---------------- host orchestration ----------------
extern "C" void kernel_launch(void* const* d_in, const int* in_sizes, int n_in,
                              void* d_out, int out_size) {
    const float* x     = (const float*)d_in[0];
    const int*   ei    = (const int*)d_in[1];
    const int*   ea    = (const int*)d_in[2];
    const int*   batch = (const int*)d_in[3];
    const float* qe    = (const float*)d_in[4];
    const float* qnW   = (const float*)d_in[5];
    const float* qnb   = (const float*)d_in[6];
    const float* W0 = (const float*)d_in[7],  *root0 = (const float*)d_in[8],  *b0 = (const float*)d_in[9];
    const float* W1 = (const float*)d_in[10], *root1 = (const float*)d_in[11], *b1 = (const float*)d_in[12];
    const float* W2 = (const float*)d_in[13], *root2 = (const float*)d_in[14], *b2 = (const float*)d_in[15];
    const float* W3 = (const float*)d_in[16], *root3 = (const float*)d_in[17], *b3 = (const float*)d_in[18];
    float* out = (float*)d_out;

    const int* src = ei;
    const int* dst = ei + EE;

    cudaFuncSetAttribute(k_gemm, cudaFuncAttributeMaxDynamicSharedMemorySize, GEMM_SMEM);

    const int MG = 782;
    const int AGG1 = 6250;    // OUT=64, WPN=1
    const int AGG2 = 12500;   // OUT=128, WPN=2

    // 1: fused prepA0 + count + prepB0 + q
    k_mega1<<<PA_BLK + CNT_BLK + PB0_BLK + Q_BLK, 256>>>(x, dst, ea, root0, W0, qe, qnW, qnb);

    // fork: CSR chain on s2, concurrent with layer-0 GEMM on legacy stream
    cudaEventRecord(g_hx.evA, (cudaStream_t)0);
    cudaStreamWaitEvent(g_hx.s2, g_hx.evA, 0);
    k_scan1<<<196, 256, 0, g_hx.s2>>>();
    k_scan23<<<196, 256, 0, g_hx.s2>>>();
    k_fill<<<(EE + 255) / 256, 256, 0, g_hx.s2>>>(src, dst, ea);
    cudaEventRecord(g_hx.evB, g_hx.s2);

    k_gemm<<<MG, 128, GEMM_SMEM>>>(b0, 64, 5);     // legacy stream, overlaps CSR
    cudaStreamWaitEvent((cudaStream_t)0, g_hx.evB, 0);   // join

    // agg layer 0 (+q fill) + prepB1
    k_agg<64, 0, 1, 128, 1><<<AGG1 + 320, 256>>>(nullptr, batch, root1, W1);
    // layer 1
    k_gemm<<<MG, 128, GEMM_SMEM>>>(b1, 128, 10);
    k_agg<128, 0, 0, 128, 2><<<AGG2 + 320, 256>>>(nullptr, nullptr, root2, W2);
    // layer 2
    k_gemm<<<MG, 128, GEMM_SMEM>>>(b2, 128, 10);
    k_agg<128, 0, 0, 64, 2><<<AGG2 + 160, 256>>>(nullptr, nullptr, root3, W3);
    // layer 3
    k_gemm<<<MG, 128, GEMM_SMEM>>>(b3, 64, 5);
    // final aggregation -> d_out
    k_agg<64, 1, 0, 0, 1><<<AGG1, 256>>>(out, nullptr, nullptr, nullptr);
}

// round 12
// speedup vs baseline: 1.0708x; 1.0708x over previous
#include <cuda_runtime.h>
#include <cuda_bf16.h>
#include <cuda_fp16.h>
#include <cstdint>

#define NN 50000
#define EE 800000
#define RR 4
#define GG 16

// ---------------- scratch (device globals; no allocation) ----------------
__device__ __half  g_Ysh[NN * 128];         // self+bias fp16 [N][out]
__device__ __half  g_Ym[NN * 512];          // messages fp16 [N][4*out] (L2-resident)
__device__ __half  g_Asp[NN * 128];         // activations fp16 [N][128]
__device__ __half  g_Bsp[128 * 640];        // weights fp16, row-major [k][5*out]
__device__ float   g_q[GG * 64];
__device__ int     g_cnt[RR * NN];          // ALWAYS zero at call entry (scan1 re-zeroes)
__device__ float   g_inv[NN * 4];
__device__ int     g_deg[NN];
__device__ int     g_part[256];
__device__ int     g_rowptr[NN + 1];
__device__ int     g_fill[NN];
__device__ int     g_csr[EE];               // src | (rel<<28)

// ---------------- helpers ----------------
__device__ __forceinline__ uint32_t smem_u32(const void* p) {
    return (uint32_t)__cvta_generic_to_shared(p);
}
__device__ __forceinline__ void ldsm4(uint32_t* d, const __half* p) {
    uint32_t a = smem_u32(p);
    asm volatile("ldmatrix.sync.aligned.m8n8.x4.shared.b16 {%0,%1,%2,%3}, [%4];"
                 : "=r"(d[0]), "=r"(d[1]), "=r"(d[2]), "=r"(d[3]) : "r"(a));
}
__device__ __forceinline__ void ldsm4t(uint32_t* d, const __half* p) {
    uint32_t a = smem_u32(p);
    asm volatile("ldmatrix.sync.aligned.m8n8.x4.trans.shared.b16 {%0,%1,%2,%3}, [%4];"
                 : "=r"(d[0]), "=r"(d[1]), "=r"(d[2]), "=r"(d[3]) : "r"(a));
}
__device__ __forceinline__ void mma16816(float* c, const uint32_t* a, uint32_t b0, uint32_t b1) {
    asm volatile(
        "mma.sync.aligned.m16n8k16.row.col.f32.f16.f16.f32 "
        "{%0,%1,%2,%3}, {%4,%5,%6,%7}, {%8,%9}, {%0,%1,%2,%3};"
        : "+f"(c[0]), "+f"(c[1]), "+f"(c[2]), "+f"(c[3])
        : "r"(a[0]), "r"(a[1]), "r"(a[2]), "r"(a[3]), "r"(b0), "r"(b1));
}
__device__ __forceinline__ void cp_async16(uint32_t smem_addr, const void* gptr) {
    asm volatile("cp.async.cg.shared.global [%0], [%1], 16;" :: "r"(smem_addr), "l"(gptr));
}
__device__ __forceinline__ void cp_commit() {
    asm volatile("cp.async.commit_group;" ::: "memory");
}
template <int N>
__device__ __forceinline__ void cp_wait() {
    asm volatile("cp.async.wait_group %0;" :: "n"(N) : "memory");
}
__device__ __forceinline__ float pick4(float4 v, int r) {
    return r == 0 ? v.x : (r == 1 ? v.y : (r == 2 ? v.z : v.w));
}

// ---------------- prepB body ----------------
__device__ __forceinline__ void prepB_body(int idx, const float* __restrict__ root,
                                           const float* __restrict__ W, int out) {
    int ncols = 5 * out;
    if (idx >= 128 * ncols) return;
    int k = idx / ncols, j = idx % ncols;
    float v = (j < out) ? root[k * out + j]
                        : W[((j / out - 1) * 128 + k) * out + (j % out)];
    g_Bsp[idx] = __float2half_rn(v);
}

// ---------------- mega1: prepA0 + edge count + prepB0 + q projection ----------------
#define PA_BLK 25000
#define CNT_BLK 3125
#define PB0_BLK 160
#define Q_BLK 16
__global__ void __launch_bounds__(256) k_mega1(
    const float* __restrict__ x, const int* __restrict__ dst, const int* __restrict__ ea,
    const float* __restrict__ root0, const float* __restrict__ W0,
    const float* __restrict__ qe, const float* __restrict__ qnW, const float* __restrict__ qnb) {
    int b = blockIdx.x, t = threadIdx.x;
    if (b < PA_BLK) {
        int idx = b * 256 + t;
        g_Asp[idx] = __float2half_rn(x[idx]);
    } else if (b < PA_BLK + CNT_BLK) {
        int e = (b - PA_BLK) * 256 + t;
        atomicAdd(&g_cnt[ea[e] * NN + dst[e]], 1);
    } else if (b < PA_BLK + CNT_BLK + PB0_BLK) {
        prepB_body((b - PA_BLK - CNT_BLK) * 256 + t, root0, W0, 64);
    } else {
        __shared__ float sq[768];
        int g = b - PA_BLK - CNT_BLK - PB0_BLK;
        for (int i = t; i < 768; i += 256) sq[i] = qe[g * 768 + i];
        __syncthreads();
        if (t < 64) {
            float acc = qnb[t];
            for (int k = 0; k < 768; k++) acc = fmaf(sq[k], qnW[k * 64 + t], acc);
            g_q[g * 64 + t] = fmaxf(acc, 0.0f);
        }
    }
}

// ---------------- CSR scans (scan1 re-zeroes g_cnt) ----------------
__global__ void k_scan1() {
    int t = threadIdx.x;
    int i = blockIdx.x * 256 + t;
    int tot = 0;
    if (i < NN) {
#pragma unroll
        for (int r = 0; r < RR; r++) {
            int c = g_cnt[r * NN + i];
            g_cnt[r * NN + i] = 0;
            tot += c;
            g_inv[i * 4 + r] = 1.0f / (float)max(c, 1);
        }
        g_deg[i] = tot;
    }
    __shared__ int s[256];
    s[t] = tot;
    __syncthreads();
    for (int d = 128; d; d >>= 1) {
        if (t < d) s[t] += s[t + d];
        __syncthreads();
    }
    if (t == 0) g_part[blockIdx.x] = s[0];
}
__global__ void k_scan23() {
    int t = threadIdx.x;
    int bid = blockIdx.x;
    __shared__ int sp[256];
    int pv = (t < 196) ? g_part[t] : 0;
    sp[t] = pv;
    __syncthreads();
    for (int d = 1; d < 256; d <<= 1) {
        int x = (t >= d) ? sp[t - d] : 0;
        __syncthreads();
        sp[t] += x;
        __syncthreads();
    }
    int base = (bid == 0) ? 0 : sp[bid - 1];
    int total = sp[195];
    __shared__ int s[256];
    int i = bid * 256 + t;
    int v = (i < NN) ? g_deg[i] : 0;
    s[t] = v;
    __syncthreads();
    for (int d = 1; d < 256; d <<= 1) {
        int x = (t >= d) ? s[t - d] : 0;
        __syncthreads();
        s[t] += x;
        __syncthreads();
    }
    if (i < NN) {
        int off = base + s[t] - v;
        g_rowptr[i] = off;
        g_fill[i] = off;
    }
    if (bid == 195 && t == 0) g_rowptr[NN] = total;
}
__global__ void k_fill(const int* __restrict__ src, const int* __restrict__ dst,
                       const int* __restrict__ ea) {
    int e = blockIdx.x * blockDim.x + threadIdx.x;
    if (e >= EE) return;
    int d = dst[e];
    int pos = atomicAdd(&g_fill[d], 1);
    g_csr[pos] = src[e] | (ea[e] << 28);
}

// ---------------- GEMM: 64-row CTAs, 64-col iters, smem-staged coalesced epilogue ----------------
#define AST 136
#define BSTn 72
#define GEMM_SMEM ((64 * AST + 128 * BSTn) * 2)   // 35.8KB -> 6 CTA/SM

__global__ void __launch_bounds__(128, 6) k_gemm(const float* __restrict__ bias,
                                                 int out, int niter) {
    extern __shared__ __half smem[];
    __half* sA = smem;                 // [64][AST]
    __half* sB = smem + 64 * AST;      // [128][BSTn]; reused as stage [64][BSTn] post-MMA
    int m0 = blockIdx.x * 64;
    int t = threadIdx.x;
    int ncols = 5 * out;

#pragma unroll
    for (int i = 0; i < 8; i++) {
        int idx = t + i * 128;
        int row = idx >> 4;
        int c8 = (idx & 15) * 8;
        int grow = m0 + row;
        uint4 val = make_uint4(0, 0, 0, 0);
        if (grow < NN) val = *(const uint4*)(g_Asp + (size_t)grow * 128 + c8);
        *(uint4*)(sA + row * AST + c8) = val;
    }

    int w = t >> 5, lane = t & 31;
    int wm = (w & 1) * 32, wn = (w >> 1) * 32;
    int lr = lane & 15, lc = lane >> 4;
    int g = lane >> 2, tg = lane & 3;
    int pitchM = 4 * out;

    for (int nb = 0; nb < niter; nb++) {
        int n0 = nb * 64;
        __syncthreads();   // prior epilogue LDS done; safe to overwrite sB
        {
            uint32_t sbb = smem_u32(sB);
#pragma unroll
            for (int i = 0; i < 8; i++) {
                int idx = t + i * 128;
                int row = idx >> 3;
                int c8 = (idx & 7) * 8;
                cp_async16(sbb + (row * BSTn + c8) * 2, g_Bsp + (size_t)row * ncols + n0 + c8);
            }
            cp_commit();
            cp_wait<0>();
        }
        __syncthreads();

        float acc[2][4][4];
#pragma unroll
        for (int mt = 0; mt < 2; mt++)
#pragma unroll
            for (int nt = 0; nt < 4; nt++)
#pragma unroll
                for (int i = 0; i < 4; i++) acc[mt][nt][i] = 0.0f;

#pragma unroll
        for (int kk = 0; kk < 8; kk++) {
            uint32_t b[2][4];
#pragma unroll
            for (int nh = 0; nh < 2; nh++)
                ldsm4t(b[nh], sB + (kk * 16 + lr) * BSTn + wn + nh * 16 + lc * 8);
            uint32_t a[2][4];
#pragma unroll
            for (int mt = 0; mt < 2; mt++)
                ldsm4(a[mt], sA + (wm + mt * 16 + lr) * AST + kk * 16 + lc * 8);
#pragma unroll
            for (int mt = 0; mt < 2; mt++)
#pragma unroll
                for (int nt = 0; nt < 4; nt++) {
                    int nh = nt >> 1, h = (nt & 1) * 2;
                    mma16816(acc[mt][nt], a[mt], b[nh][h], b[nh][h + 1]);
                }
        }

        bool isSelf = (n0 < out);
        __syncthreads();   // all ldsm on sB done; reuse sB[0..64) rows as stage
        // STS: acc fragments (+bias on self) -> stage[64][BSTn]
#pragma unroll
        for (int mt = 0; mt < 2; mt++) {
#pragma unroll
            for (int nt = 0; nt < 4; nt++) {
                int scol = wn + nt * 8 + tg * 2;
                float b0 = 0.0f, b1 = 0.0f;
                if (isSelf) { b0 = bias[n0 + scol]; b1 = bias[n0 + scol + 1]; }
                int sr0 = wm + mt * 16 + g;
                *(__half2*)(sB + sr0 * BSTn + scol) =
                    __floats2half2_rn(acc[mt][nt][0] + b0, acc[mt][nt][1] + b1);
                *(__half2*)(sB + (sr0 + 8) * BSTn + scol) =
                    __floats2half2_rn(acc[mt][nt][2] + b0, acc[mt][nt][3] + b1);
            }
        }
        __syncthreads();
        // coalesced row stores: 64 rows x 8 uint4 = 512, 4 per thread
#pragma unroll
        for (int i = 0; i < 4; i++) {
            int idx = t + i * 128;
            int row = idx >> 3;
            int q8 = (idx & 7) * 8;
            int grow = m0 + row;
            if (grow < NN) {
                uint4 val = *(const uint4*)(sB + row * BSTn + q8);
                if (isSelf)
                    *(uint4*)(g_Ysh + (size_t)grow * out + n0 + q8) = val;
                else
                    *(uint4*)(g_Ym + (size_t)grow * pitchM + (n0 - out) + q8) = val;
            }
        }
    }
}

// ---------------- aggregation: WPN warps/node, 2 cols/lane ----------------
template <int OUT, int MODE, int QF, int NXT, int WPN>
__global__ void __launch_bounds__(256) k_agg(float* __restrict__ Optr,
                                             const int* __restrict__ batch,
                                             const float* __restrict__ root,
                                             const float* __restrict__ W) {
    constexpr int AGGB = (NN * WPN * 32 + 255) / 256;
    if (NXT > 0 && blockIdx.x >= AGGB) {
        prepB_body((blockIdx.x - AGGB) * 256 + threadIdx.x, root, W, NXT);
        return;
    }
    int gw = (blockIdx.x * 256 + threadIdx.x) >> 5;
    int w = (WPN == 2) ? (gw >> 1) : gw;
    int colbase = (WPN == 2) ? (gw & 1) * 64 : 0;
    if (w >= NN) return;
    int lane = threadIdx.x & 31;
    constexpr int PITCH = 4 * OUT;
    int start = g_rowptr[w], end = g_rowptr[w + 1];
    float4 iv4 = *(const float4*)(g_inv + w * 4);
    int co = colbase + lane * 2;

    float acc0, acc1;
    {
        uint32_t s = *(const uint32_t*)(g_Ysh + (size_t)w * OUT + co);
        float2 s0 = __half22float2(*(__half2*)&s);
        acc0 = s0.x; acc1 = s0.y;
    }

    int e = start;
    for (; e + 8 <= end; e += 8) {
        int u[8];
#pragma unroll
        for (int j = 0; j < 8; j++) u[j] = g_csr[e + j];
        const __half* p[8];
        float iv[8];
#pragma unroll
        for (int j = 0; j < 8; j++) {
            int s = u[j] & 0x0FFFFFFF;
            int r = ((unsigned)u[j]) >> 28;
            p[j] = g_Ym + (size_t)s * PITCH + r * OUT + co;
            iv[j] = pick4(iv4, r);
        }
        uint32_t d[8];
#pragma unroll
        for (int j = 0; j < 8; j++) d[j] = *(const uint32_t*)p[j];
#pragma unroll
        for (int j = 0; j < 8; j++) {
            float2 m0 = __half22float2(*(__half2*)&d[j]);
            acc0 += m0.x * iv[j]; acc1 += m0.y * iv[j];
        }
    }
    for (; e < end; e++) {
        int u0 = g_csr[e];
        int s0 = u0 & 0x0FFFFFFF, r0 = ((unsigned)u0) >> 28;
        uint32_t d0 = *(const uint32_t*)(g_Ym + (size_t)s0 * PITCH + r0 * OUT + co);
        float i0 = pick4(iv4, r0);
        float2 m0 = __half22float2(*(__half2*)&d0);
        acc0 += m0.x * i0; acc1 += m0.y * i0;
    }

    if constexpr (MODE == 0) {
        __half2 ph = __floats2half2_rn(fmaxf(acc0, 0.0f), fmaxf(acc1, 0.0f));
        *(__half2*)(g_Asp + (size_t)w * 128 + co) = ph;
        if constexpr (QF) {
            int b = batch[w];
            __half2 hh;
            hh.x = __float2half_rn(g_q[b * 64 + lane * 2]);
            hh.y = __float2half_rn(g_q[b * 64 + lane * 2 + 1]);
            *(__half2*)(g_Asp + (size_t)w * 128 + 64 + lane * 2) = hh;
        }
    } else {
        float2 r; r.x = acc0; r.y = acc1;
        *(float2*)(Optr + (size_t)w * OUT + co) = r;
    }
}

// ---------------- host orchestration ----------------
extern "C" void kernel_launch(void* const* d_in, const int* in_sizes, int n_in,
                              void* d_out, int out_size) {
    const float* x     = (const float*)d_in[0];
    const int*   ei    = (const int*)d_in[1];
    const int*   ea    = (const int*)d_in[2];
    const int*   batch = (const int*)d_in[3];
    const float* qe    = (const float*)d_in[4];
    const float* qnW   = (const float*)d_in[5];
    const float* qnb   = (const float*)d_in[6];
    const float* W0 = (const float*)d_in[7],  *root0 = (const float*)d_in[8],  *b0 = (const float*)d_in[9];
    const float* W1 = (const float*)d_in[10], *root1 = (const float*)d_in[11], *b1 = (const float*)d_in[12];
    const float* W2 = (const float*)d_in[13], *root2 = (const float*)d_in[14], *b2 = (const float*)d_in[15];
    const float* W3 = (const float*)d_in[16], *root3 = (const float*)d_in[17], *b3 = (const float*)d_in[18];
    float* out = (float*)d_out;

    const int* src = ei;
    const int* dst = ei + EE;

    cudaFuncSetAttribute(k_gemm, cudaFuncAttributeMaxDynamicSharedMemorySize, GEMM_SMEM);

    const int MG = 782;
    const int AGG1 = 6250;    // OUT=64, WPN=1
    const int AGG2 = 12500;   // OUT=128, WPN=2

    // 1: fused prepA0 + count + prepB0 + q
    k_mega1<<<PA_BLK + CNT_BLK + PB0_BLK + Q_BLK, 256>>>(x, dst, ea, root0, W0, qe, qnW, qnb);
    k_scan1<<<196, 256>>>();                                   // 2
    k_scan23<<<196, 256>>>();                                  // 3
    k_gemm<<<MG, 128, GEMM_SMEM>>>(b0, 64, 5);                 // 4 (profiled)
    k_fill<<<(EE + 255) / 256, 256>>>(src, dst, ea);           // 5

    // 6: agg layer 0 (+q fill) + prepB1
    k_agg<64, 0, 1, 128, 1><<<AGG1 + 320, 256>>>(nullptr, batch, root1, W1);
    // 7: layer 1
    k_gemm<<<MG, 128, GEMM_SMEM>>>(b1, 128, 10);
    // 8: agg layer 1 + prepB2
    k_agg<128, 0, 0, 128, 2><<<AGG2 + 320, 256>>>(nullptr, nullptr, root2, W2);
    // 9: layer 2
    k_gemm<<<MG, 128, GEMM_SMEM>>>(b2, 128, 10);
    // 10: agg layer 2 + prepB3
    k_agg<128, 0, 0, 64, 2><<<AGG2 + 160, 256>>>(nullptr, nullptr, root3, W3);
    // 11: layer 3
    k_gemm<<<MG, 128, GEMM_SMEM>>>(b3, 64, 5);
    // 12: final aggregation -> d_out
    k_agg<64, 1, 0, 0, 1><<<AGG1, 256>>>(out, nullptr, nullptr, nullptr);
}

// round 13
// speedup vs baseline: 1.2485x; 1.1659x over previous
#include <cuda_runtime.h>
#include <cuda_bf16.h>
#include <cuda_fp16.h>
#include <cstdint>

#define NN 50000
#define EE 800000
#define RR 4
#define GG 16

// ---------------- scratch (device globals; no allocation) ----------------
__device__ __half  g_Ysh[NN * 128];         // self+bias fp16 [N][out]
__device__ __half  g_Ym[NN * 512];          // messages fp16 [N][4*out] (L2-resident)
__device__ __half  g_Asp[NN * 128];         // activations fp16 [N][128]
__device__ __half  g_Bsp[128 * 640];        // weights fp16, row-major [k][5*out]
__device__ float   g_q[GG * 64];
__device__ int     g_cnt[RR * NN];          // ALWAYS zero at call entry (scan1 re-zeroes)
__device__ float   g_inv[NN * 4];
__device__ int     g_deg[NN];
__device__ int     g_part[256];
__device__ int     g_rowptr[NN + 1];
__device__ int     g_fill[NN];
__device__ int     g_csr[EE];               // src | (rel<<28)

// ---------------- helpers ----------------
__device__ __forceinline__ uint32_t smem_u32(const void* p) {
    return (uint32_t)__cvta_generic_to_shared(p);
}
__device__ __forceinline__ void ldsm4(uint32_t* d, const __half* p) {
    uint32_t a = smem_u32(p);
    asm volatile("ldmatrix.sync.aligned.m8n8.x4.shared.b16 {%0,%1,%2,%3}, [%4];"
                 : "=r"(d[0]), "=r"(d[1]), "=r"(d[2]), "=r"(d[3]) : "r"(a));
}
__device__ __forceinline__ void ldsm4t(uint32_t* d, const __half* p) {
    uint32_t a = smem_u32(p);
    asm volatile("ldmatrix.sync.aligned.m8n8.x4.trans.shared.b16 {%0,%1,%2,%3}, [%4];"
                 : "=r"(d[0]), "=r"(d[1]), "=r"(d[2]), "=r"(d[3]) : "r"(a));
}
__device__ __forceinline__ void mma16816(float* c, const uint32_t* a, uint32_t b0, uint32_t b1) {
    asm volatile(
        "mma.sync.aligned.m16n8k16.row.col.f32.f16.f16.f32 "
        "{%0,%1,%2,%3}, {%4,%5,%6,%7}, {%8,%9}, {%0,%1,%2,%3};"
        : "+f"(c[0]), "+f"(c[1]), "+f"(c[2]), "+f"(c[3])
        : "r"(a[0]), "r"(a[1]), "r"(a[2]), "r"(a[3]), "r"(b0), "r"(b1));
}
__device__ __forceinline__ void cp_async16(uint32_t smem_addr, const void* gptr) {
    asm volatile("cp.async.cg.shared.global [%0], [%1], 16;" :: "r"(smem_addr), "l"(gptr));
}
__device__ __forceinline__ void cp_commit() {
    asm volatile("cp.async.commit_group;" ::: "memory");
}
template <int N>
__device__ __forceinline__ void cp_wait() {
    asm volatile("cp.async.wait_group %0;" :: "n"(N) : "memory");
}
__device__ __forceinline__ float pick4(float4 v, int r) {
    return r == 0 ? v.x : (r == 1 ? v.y : (r == 2 ? v.z : v.w));
}

// ---------------- prepB body ----------------
__device__ __forceinline__ void prepB_body(int idx, const float* __restrict__ root,
                                           const float* __restrict__ W, int out) {
    int ncols = 5 * out;
    if (idx >= 128 * ncols) return;
    int k = idx / ncols, j = idx % ncols;
    float v = (j < out) ? root[k * out + j]
                        : W[((j / out - 1) * 128 + k) * out + (j % out)];
    g_Bsp[idx] = __float2half_rn(v);
}

// ---------------- mega1: prepA0 + edge count + prepB0 + q projection ----------------
#define PA_BLK 25000
#define CNT_BLK 3125
#define PB0_BLK 160
#define Q_BLK 16
__global__ void __launch_bounds__(256) k_mega1(
    const float* __restrict__ x, const int* __restrict__ dst, const int* __restrict__ ea,
    const float* __restrict__ root0, const float* __restrict__ W0,
    const float* __restrict__ qe, const float* __restrict__ qnW, const float* __restrict__ qnb) {
    int b = blockIdx.x, t = threadIdx.x;
    if (b < PA_BLK) {
        int idx = b * 256 + t;
        g_Asp[idx] = __float2half_rn(x[idx]);
    } else if (b < PA_BLK + CNT_BLK) {
        int e = (b - PA_BLK) * 256 + t;
        atomicAdd(&g_cnt[ea[e] * NN + dst[e]], 1);
    } else if (b < PA_BLK + CNT_BLK + PB0_BLK) {
        prepB_body((b - PA_BLK - CNT_BLK) * 256 + t, root0, W0, 64);
    } else {
        __shared__ float sq[768];
        int g = b - PA_BLK - CNT_BLK - PB0_BLK;
        for (int i = t; i < 768; i += 256) sq[i] = qe[g * 768 + i];
        __syncthreads();
        if (t < 64) {
            float acc = qnb[t];
            for (int k = 0; k < 768; k++) acc = fmaf(sq[k], qnW[k * 64 + t], acc);
            g_q[g * 64 + t] = fmaxf(acc, 0.0f);
        }
    }
}

// ---------------- CSR scans (scan1 re-zeroes g_cnt) ----------------
__global__ void k_scan1() {
    int t = threadIdx.x;
    int i = blockIdx.x * 256 + t;
    int tot = 0;
    if (i < NN) {
#pragma unroll
        for (int r = 0; r < RR; r++) {
            int c = g_cnt[r * NN + i];
            g_cnt[r * NN + i] = 0;
            tot += c;
            g_inv[i * 4 + r] = 1.0f / (float)max(c, 1);
        }
        g_deg[i] = tot;
    }
    __shared__ int s[256];
    s[t] = tot;
    __syncthreads();
    for (int d = 128; d; d >>= 1) {
        if (t < d) s[t] += s[t + d];
        __syncthreads();
    }
    if (t == 0) g_part[blockIdx.x] = s[0];
}
__global__ void k_scan23() {
    int t = threadIdx.x;
    int bid = blockIdx.x;
    __shared__ int sp[256];
    int pv = (t < 196) ? g_part[t] : 0;
    sp[t] = pv;
    __syncthreads();
    for (int d = 1; d < 256; d <<= 1) {
        int x = (t >= d) ? sp[t - d] : 0;
        __syncthreads();
        sp[t] += x;
        __syncthreads();
    }
    int base = (bid == 0) ? 0 : sp[bid - 1];
    int total = sp[195];
    __shared__ int s[256];
    int i = bid * 256 + t;
    int v = (i < NN) ? g_deg[i] : 0;
    s[t] = v;
    __syncthreads();
    for (int d = 1; d < 256; d <<= 1) {
        int x = (t >= d) ? s[t - d] : 0;
        __syncthreads();
        s[t] += x;
        __syncthreads();
    }
    if (i < NN) {
        int off = base + s[t] - v;
        g_rowptr[i] = off;
        g_fill[i] = off;
    }
    if (bid == 195 && t == 0) g_rowptr[NN] = total;
}
__global__ void k_fill(const int* __restrict__ src, const int* __restrict__ dst,
                       const int* __restrict__ ea) {
    int e = blockIdx.x * blockDim.x + threadIdx.x;
    if (e >= EE) return;
    int d = dst[e];
    int pos = atomicAdd(&g_fill[d], 1);
    g_csr[pos] = src[e] | (ea[e] << 28);
}

// ---------------- GEMM: 64-row CTAs, 64-col iters, smem-staged coalesced epilogue ----------------
#define AST 136
#define BSTn 72
#define GEMM_SMEM ((64 * AST + 128 * BSTn) * 2)   // 35.8KB -> 6 CTA/SM

__global__ void __launch_bounds__(128, 6) k_gemm(const float* __restrict__ bias,
                                                 int out, int niter) {
    extern __shared__ __half smem[];
    __half* sA = smem;                 // [64][AST]
    __half* sB = smem + 64 * AST;      // [128][BSTn]; reused as stage [64][BSTn] post-MMA
    int m0 = blockIdx.x * 64;
    int t = threadIdx.x;
    int ncols = 5 * out;

#pragma unroll
    for (int i = 0; i < 8; i++) {
        int idx = t + i * 128;
        int row = idx >> 4;
        int c8 = (idx & 15) * 8;
        int grow = m0 + row;
        uint4 val = make_uint4(0, 0, 0, 0);
        if (grow < NN) val = *(const uint4*)(g_Asp + (size_t)grow * 128 + c8);
        *(uint4*)(sA + row * AST + c8) = val;
    }

    int w = t >> 5, lane = t & 31;
    int wm = (w & 1) * 32, wn = (w >> 1) * 32;
    int lr = lane & 15, lc = lane >> 4;
    int g = lane >> 2, tg = lane & 3;
    int pitchM = 4 * out;

    for (int nb = 0; nb < niter; nb++) {
        int n0 = nb * 64;
        __syncthreads();   // prior epilogue LDS done; safe to overwrite sB
        {
            uint32_t sbb = smem_u32(sB);
#pragma unroll
            for (int i = 0; i < 8; i++) {
                int idx = t + i * 128;
                int row = idx >> 3;
                int c8 = (idx & 7) * 8;
                cp_async16(sbb + (row * BSTn + c8) * 2, g_Bsp + (size_t)row * ncols + n0 + c8);
            }
            cp_commit();
            cp_wait<0>();
        }
        __syncthreads();

        float acc[2][4][4];
#pragma unroll
        for (int mt = 0; mt < 2; mt++)
#pragma unroll
            for (int nt = 0; nt < 4; nt++)
#pragma unroll
                for (int i = 0; i < 4; i++) acc[mt][nt][i] = 0.0f;

#pragma unroll
        for (int kk = 0; kk < 8; kk++) {
            uint32_t b[2][4];
#pragma unroll
            for (int nh = 0; nh < 2; nh++)
                ldsm4t(b[nh], sB + (kk * 16 + lr) * BSTn + wn + nh * 16 + lc * 8);
            uint32_t a[2][4];
#pragma unroll
            for (int mt = 0; mt < 2; mt++)
                ldsm4(a[mt], sA + (wm + mt * 16 + lr) * AST + kk * 16 + lc * 8);
#pragma unroll
            for (int mt = 0; mt < 2; mt++)
#pragma unroll
                for (int nt = 0; nt < 4; nt++) {
                    int nh = nt >> 1, h = (nt & 1) * 2;
                    mma16816(acc[mt][nt], a[mt], b[nh][h], b[nh][h + 1]);
                }
        }

        bool isSelf = (n0 < out);
        __syncthreads();   // all ldsm on sB done; reuse sB[0..64) rows as stage
#pragma unroll
        for (int mt = 0; mt < 2; mt++) {
#pragma unroll
            for (int nt = 0; nt < 4; nt++) {
                int scol = wn + nt * 8 + tg * 2;
                float b0 = 0.0f, b1 = 0.0f;
                if (isSelf) { b0 = bias[n0 + scol]; b1 = bias[n0 + scol + 1]; }
                int sr0 = wm + mt * 16 + g;
                *(__half2*)(sB + sr0 * BSTn + scol) =
                    __floats2half2_rn(acc[mt][nt][0] + b0, acc[mt][nt][1] + b1);
                *(__half2*)(sB + (sr0 + 8) * BSTn + scol) =
                    __floats2half2_rn(acc[mt][nt][2] + b0, acc[mt][nt][3] + b1);
            }
        }
        __syncthreads();
        // coalesced row stores: 64 rows x 8 uint4 = 512, 4 per thread
#pragma unroll
        for (int i = 0; i < 4; i++) {
            int idx = t + i * 128;
            int row = idx >> 3;
            int q8 = (idx & 7) * 8;
            int grow = m0 + row;
            if (grow < NN) {
                uint4 val = *(const uint4*)(sB + row * BSTn + q8);
                if (isSelf)
                    *(uint4*)(g_Ysh + (size_t)grow * out + n0 + q8) = val;
                else
                    *(uint4*)(g_Ym + (size_t)grow * pitchM + (n0 - out) + q8) = val;
            }
        }
    }
}

// ---------------- aggregation: one warp per node, 8-unrolled gather ----------------
#define AGG_BLK 6250
template <int OUT, int MODE, int QF, int NXT>
__global__ void __launch_bounds__(256) k_agg(float* __restrict__ Optr,
                                             const int* __restrict__ batch,
                                             const float* __restrict__ root,
                                             const float* __restrict__ W) {
    if (NXT > 0 && blockIdx.x >= AGG_BLK) {
        prepB_body((blockIdx.x - AGG_BLK) * 256 + threadIdx.x, root, W, NXT);
        return;
    }
    int w = (blockIdx.x * 256 + threadIdx.x) >> 5;
    if (w >= NN) return;
    int lane = threadIdx.x & 31;
    constexpr int V = OUT / 32;
    constexpr int PITCH = 4 * OUT;
    int start = g_rowptr[w], end = g_rowptr[w + 1];
    float4 iv4 = *(const float4*)(g_inv + w * 4);

    float acc[V];
    {
        const __half* sp = g_Ysh + (size_t)w * OUT + lane * V;
        if constexpr (V == 4) {
            uint2 s = *(const uint2*)sp;
            float2 s0 = __half22float2(*(__half2*)&s.x);
            float2 s1 = __half22float2(*(__half2*)&s.y);
            acc[0] = s0.x; acc[1] = s0.y; acc[2] = s1.x; acc[3] = s1.y;
        } else {
            uint32_t s = *(const uint32_t*)sp;
            float2 s0 = __half22float2(*(__half2*)&s);
            acc[0] = s0.x; acc[1] = s0.y;
        }
    }

    int e = start;
    for (; e + 8 <= end; e += 8) {
        int u[8];
#pragma unroll
        for (int j = 0; j < 8; j++) u[j] = g_csr[e + j];
        const __half* p[8];
        float iv[8];
#pragma unroll
        for (int j = 0; j < 8; j++) {
            int s = u[j] & 0x0FFFFFFF;
            int r = ((unsigned)u[j]) >> 28;
            p[j] = g_Ym + (size_t)s * PITCH + r * OUT + lane * V;
            iv[j] = pick4(iv4, r);
        }
        if constexpr (V == 4) {
            uint2 d[8];
#pragma unroll
            for (int j = 0; j < 8; j++) d[j] = *(const uint2*)p[j];
#pragma unroll
            for (int j = 0; j < 8; j++) {
                float2 m0 = __half22float2(*(__half2*)&d[j].x);
                float2 m1 = __half22float2(*(__half2*)&d[j].y);
                acc[0] += m0.x * iv[j]; acc[1] += m0.y * iv[j];
                acc[2] += m1.x * iv[j]; acc[3] += m1.y * iv[j];
            }
        } else {
            uint32_t d[8];
#pragma unroll
            for (int j = 0; j < 8; j++) d[j] = *(const uint32_t*)p[j];
#pragma unroll
            for (int j = 0; j < 8; j++) {
                float2 m0 = __half22float2(*(__half2*)&d[j]);
                acc[0] += m0.x * iv[j]; acc[1] += m0.y * iv[j];
            }
        }
    }
    for (; e < end; e++) {
        int u0 = g_csr[e];
        int s0 = u0 & 0x0FFFFFFF, r0 = ((unsigned)u0) >> 28;
        const __half* p0 = g_Ym + (size_t)s0 * PITCH + r0 * OUT + lane * V;
        float i0 = pick4(iv4, r0);
        if constexpr (V == 4) {
            uint2 w0 = *(const uint2*)p0;
            float2 a0 = __half22float2(*(__half2*)&w0.x);
            float2 a1 = __half22float2(*(__half2*)&w0.y);
            acc[0] += a0.x * i0; acc[1] += a0.y * i0;
            acc[2] += a1.x * i0; acc[3] += a1.y * i0;
        } else {
            uint32_t w0 = *(const uint32_t*)p0;
            float2 a0 = __half22float2(*(__half2*)&w0);
            acc[0] += a0.x * i0; acc[1] += a0.y * i0;
        }
    }

    if constexpr (MODE == 0) {
        union { __half h[V]; uint2 u2; uint32_t u1; } ph;
#pragma unroll
        for (int j = 0; j < V; j++)
            ph.h[j] = __float2half_rn(fmaxf(acc[j], 0.0f));
        __half* base = g_Asp + (size_t)w * 128 + lane * V;
        if constexpr (V == 4) *(uint2*)base = ph.u2;
        else                  *(uint32_t*)base = ph.u1;
        if constexpr (QF) {
            int b = batch[w];
            __half2 hh;
            hh.x = __float2half_rn(g_q[b * 64 + lane * 2]);
            hh.y = __float2half_rn(g_q[b * 64 + lane * 2 + 1]);
            *(__half2*)(g_Asp + (size_t)w * 128 + 64 + lane * 2) = hh;
        }
    } else {
        float* op = Optr + (size_t)w * OUT + lane * V;
        if constexpr (V == 4) {
            float4 r; r.x = acc[0]; r.y = acc[1]; r.z = acc[2]; r.w = acc[3];
            *(float4*)op = r;
        } else {
            float2 r; r.x = acc[0]; r.y = acc[1];
            *(float2*)op = r;
        }
    }
}

// ---------------- host orchestration ----------------
extern "C" void kernel_launch(void* const* d_in, const int* in_sizes, int n_in,
                              void* d_out, int out_size) {
    const float* x     = (const float*)d_in[0];
    const int*   ei    = (const int*)d_in[1];
    const int*   ea    = (const int*)d_in[2];
    const int*   batch = (const int*)d_in[3];
    const float* qe    = (const float*)d_in[4];
    const float* qnW   = (const float*)d_in[5];
    const float* qnb   = (const float*)d_in[6];
    const float* W0 = (const float*)d_in[7],  *root0 = (const float*)d_in[8],  *b0 = (const float*)d_in[9];
    const float* W1 = (const float*)d_in[10], *root1 = (const float*)d_in[11], *b1 = (const float*)d_in[12];
    const float* W2 = (const float*)d_in[13], *root2 = (const float*)d_in[14], *b2 = (const float*)d_in[15];
    const float* W3 = (const float*)d_in[16], *root3 = (const float*)d_in[17], *b3 = (const float*)d_in[18];
    float* out = (float*)d_out;

    const int* src = ei;
    const int* dst = ei + EE;

    cudaFuncSetAttribute(k_gemm, cudaFuncAttributeMaxDynamicSharedMemorySize, GEMM_SMEM);

    const int MG = 782;

    // 1: fused prepA0 + count + prepB0 + q
    k_mega1<<<PA_BLK + CNT_BLK + PB0_BLK + Q_BLK, 256>>>(x, dst, ea, root0, W0, qe, qnW, qnb);
    k_scan1<<<196, 256>>>();                                   // 2
    k_scan23<<<196, 256>>>();                                  // 3
    k_gemm<<<MG, 128, GEMM_SMEM>>>(b0, 64, 5);                 // 4 (profiled)
    k_fill<<<(EE + 255) / 256, 256>>>(src, dst, ea);           // 5

    // 6: agg layer 0 (+q fill) + prepB1
    k_agg<64, 0, 1, 128><<<AGG_BLK + 320, 256>>>(nullptr, batch, root1, W1);
    // 7: layer 1
    k_gemm<<<MG, 128, GEMM_SMEM>>>(b1, 128, 10);
    // 8: agg layer 1 + prepB2
    k_agg<128, 0, 0, 128><<<AGG_BLK + 320, 256>>>(nullptr, nullptr, root2, W2);
    // 9: layer 2
    k_gemm<<<MG, 128, GEMM_SMEM>>>(b2, 128, 10);
    // 10: agg layer 2 + prepB3
    k_agg<128, 0, 0, 64><<<AGG_BLK + 160, 256>>>(nullptr, nullptr, root3, W3);
    // 11: layer 3
    k_gemm<<<MG, 128, GEMM_SMEM>>>(b3, 64, 5);
    // 12: final aggregation -> d_out
    k_agg<64, 1, 0, 0><<<AGG_BLK, 256>>>(out, nullptr, nullptr, nullptr);
}

// round 14
// speedup vs baseline: 1.3032x; 1.0438x over previous
#include <cuda_runtime.h>
#include <cuda_bf16.h>
#include <cuda_fp16.h>
#include <cstdint>

#define NN 50000
#define EE 800000
#define RR 4
#define GG 16
#define MG 782   // ceil(NN/64) gemm M-tiles

// ---------------- scratch (device globals; no allocation) ----------------
__device__ __half  g_Ysh[NN * 128];         // self+bias fp16 [N][out]
__device__ __half  g_Ym[NN * 512];          // messages fp16 [N][4*out] (L2-resident)
__device__ __half  g_Asp[NN * 128];         // activations fp16 [N][128]
__device__ __half  g_Bsp[128 * 640];        // weights fp16, row-major [k][5*out]
__device__ float   g_q[GG * 64];
__device__ int     g_cnt[RR * NN];          // ALWAYS zero at call entry (scan1 re-zeroes)
__device__ float   g_inv[NN * 4];
__device__ int     g_deg[NN];
__device__ int     g_part[256];
__device__ int     g_rowptr[NN + 1];
__device__ int     g_fill[NN];
__device__ int     g_csr[EE];               // src | (rel<<28)

// ---------------- helpers ----------------
__device__ __forceinline__ uint32_t smem_u32(const void* p) {
    return (uint32_t)__cvta_generic_to_shared(p);
}
__device__ __forceinline__ void ldsm4(uint32_t* d, const __half* p) {
    uint32_t a = smem_u32(p);
    asm volatile("ldmatrix.sync.aligned.m8n8.x4.shared.b16 {%0,%1,%2,%3}, [%4];"
                 : "=r"(d[0]), "=r"(d[1]), "=r"(d[2]), "=r"(d[3]) : "r"(a));
}
__device__ __forceinline__ void ldsm4t(uint32_t* d, const __half* p) {
    uint32_t a = smem_u32(p);
    asm volatile("ldmatrix.sync.aligned.m8n8.x4.trans.shared.b16 {%0,%1,%2,%3}, [%4];"
                 : "=r"(d[0]), "=r"(d[1]), "=r"(d[2]), "=r"(d[3]) : "r"(a));
}
__device__ __forceinline__ void mma16816(float* c, const uint32_t* a, uint32_t b0, uint32_t b1) {
    asm volatile(
        "mma.sync.aligned.m16n8k16.row.col.f32.f16.f16.f32 "
        "{%0,%1,%2,%3}, {%4,%5,%6,%7}, {%8,%9}, {%0,%1,%2,%3};"
        : "+f"(c[0]), "+f"(c[1]), "+f"(c[2]), "+f"(c[3])
        : "r"(a[0]), "r"(a[1]), "r"(a[2]), "r"(a[3]), "r"(b0), "r"(b1));
}
__device__ __forceinline__ void cp_async16(uint32_t smem_addr, const void* gptr) {
    asm volatile("cp.async.cg.shared.global [%0], [%1], 16;" :: "r"(smem_addr), "l"(gptr));
}
__device__ __forceinline__ void cp_commit() {
    asm volatile("cp.async.commit_group;" ::: "memory");
}
template <int N>
__device__ __forceinline__ void cp_wait() {
    asm volatile("cp.async.wait_group %0;" :: "n"(N) : "memory");
}
__device__ __forceinline__ float pick4(float4 v, int r) {
    return r == 0 ? v.x : (r == 1 ? v.y : (r == 2 ? v.z : v.w));
}

// ---------------- prepB body ----------------
__device__ __forceinline__ void prepB_body(int idx, const float* __restrict__ root,
                                           const float* __restrict__ W, int out) {
    int ncols = 5 * out;
    if (idx >= 128 * ncols) return;
    int k = idx / ncols, j = idx % ncols;
    float v = (j < out) ? root[k * out + j]
                        : W[((j / out - 1) * 128 + k) * out + (j % out)];
    g_Bsp[idx] = __float2half_rn(v);
}

// ---------------- mega1: prepA0(vec4) + edge count + prepB0 + q projection ----------------
#define PA_BLK 6250     // NN*128/(256*4)
#define CNT_BLK 3125    // EE/256
#define PB0_BLK 160     // 128*320/256
#define Q_BLK 16
__global__ void __launch_bounds__(256) k_mega1(
    const float* __restrict__ x, const int* __restrict__ dst, const int* __restrict__ ea,
    const float* __restrict__ root0, const float* __restrict__ W0,
    const float* __restrict__ qe, const float* __restrict__ qnW, const float* __restrict__ qnb) {
    int b = blockIdx.x, t = threadIdx.x;
    if (b < PA_BLK) {
        int idx4 = (b * 256 + t) * 4;
        float4 v = *(const float4*)(x + idx4);
        __half2 h0 = __floats2half2_rn(v.x, v.y);
        __half2 h1 = __floats2half2_rn(v.z, v.w);
        uint2 pk;
        pk.x = *(uint32_t*)&h0;
        pk.y = *(uint32_t*)&h1;
        *(uint2*)(g_Asp + idx4) = pk;
    } else if (b < PA_BLK + CNT_BLK) {
        int e = (b - PA_BLK) * 256 + t;
        atomicAdd(&g_cnt[ea[e] * NN + dst[e]], 1);
    } else if (b < PA_BLK + CNT_BLK + PB0_BLK) {
        prepB_body((b - PA_BLK - CNT_BLK) * 256 + t, root0, W0, 64);
    } else {
        __shared__ float sq[768];
        int g = b - PA_BLK - CNT_BLK - PB0_BLK;
        for (int i = t; i < 768; i += 256) sq[i] = qe[g * 768 + i];
        __syncthreads();
        if (t < 64) {
            float acc = qnb[t];
            for (int k = 0; k < 768; k++) acc = fmaf(sq[k], qnW[k * 64 + t], acc);
            g_q[g * 64 + t] = fmaxf(acc, 0.0f);
        }
    }
}

// ---------------- CSR scans (scan1 re-zeroes g_cnt) ----------------
__global__ void k_scan1() {
    int t = threadIdx.x;
    int i = blockIdx.x * 256 + t;
    int tot = 0;
    if (i < NN) {
#pragma unroll
        for (int r = 0; r < RR; r++) {
            int c = g_cnt[r * NN + i];
            g_cnt[r * NN + i] = 0;
            tot += c;
            g_inv[i * 4 + r] = 1.0f / (float)max(c, 1);
        }
        g_deg[i] = tot;
    }
    __shared__ int s[256];
    s[t] = tot;
    __syncthreads();
    for (int d = 128; d; d >>= 1) {
        if (t < d) s[t] += s[t + d];
        __syncthreads();
    }
    if (t == 0) g_part[blockIdx.x] = s[0];
}
__global__ void k_scan23() {
    int t = threadIdx.x;
    int bid = blockIdx.x;
    __shared__ int sp[256];
    int pv = (t < 196) ? g_part[t] : 0;
    sp[t] = pv;
    __syncthreads();
    for (int d = 1; d < 256; d <<= 1) {
        int x = (t >= d) ? sp[t - d] : 0;
        __syncthreads();
        sp[t] += x;
        __syncthreads();
    }
    int base = (bid == 0) ? 0 : sp[bid - 1];
    int total = sp[195];
    __shared__ int s[256];
    int i = bid * 256 + t;
    int v = (i < NN) ? g_deg[i] : 0;
    s[t] = v;
    __syncthreads();
    for (int d = 1; d < 256; d <<= 1) {
        int x = (t >= d) ? s[t - d] : 0;
        __syncthreads();
        s[t] += x;
        __syncthreads();
    }
    if (i < NN) {
        int off = base + s[t] - v;
        g_rowptr[i] = off;
        g_fill[i] = off;
    }
    if (bid == 195 && t == 0) g_rowptr[NN] = total;
}

// ---------------- GEMM body (shared): 64-row CTA, 64-col iters, staged epilogue ----------------
#define AST 136
#define BSTn 72
#define GEMM_SMEM ((64 * AST + 128 * BSTn) * 2)   // 35.8KB -> 6 CTA/SM

__device__ void gemm_body(const float* __restrict__ bias, int out, int niter,
                          int bid, __half* smem) {
    __half* sA = smem;                 // [64][AST]
    __half* sB = smem + 64 * AST;      // [128][BSTn]; reused as stage post-MMA
    int m0 = bid * 64;
    int t = threadIdx.x;
    int ncols = 5 * out;

#pragma unroll
    for (int i = 0; i < 8; i++) {
        int idx = t + i * 128;
        int row = idx >> 4;
        int c8 = (idx & 15) * 8;
        int grow = m0 + row;
        uint4 val = make_uint4(0, 0, 0, 0);
        if (grow < NN) val = *(const uint4*)(g_Asp + (size_t)grow * 128 + c8);
        *(uint4*)(sA + row * AST + c8) = val;
    }

    int w = t >> 5, lane = t & 31;
    int wm = (w & 1) * 32, wn = (w >> 1) * 32;
    int lr = lane & 15, lc = lane >> 4;
    int g = lane >> 2, tg = lane & 3;
    int pitchM = 4 * out;

    for (int nb = 0; nb < niter; nb++) {
        int n0 = nb * 64;
        __syncthreads();
        {
            uint32_t sbb = smem_u32(sB);
#pragma unroll
            for (int i = 0; i < 8; i++) {
                int idx = t + i * 128;
                int row = idx >> 3;
                int c8 = (idx & 7) * 8;
                cp_async16(sbb + (row * BSTn + c8) * 2, g_Bsp + (size_t)row * ncols + n0 + c8);
            }
            cp_commit();
            cp_wait<0>();
        }
        __syncthreads();

        float acc[2][4][4];
#pragma unroll
        for (int mt = 0; mt < 2; mt++)
#pragma unroll
            for (int nt = 0; nt < 4; nt++)
#pragma unroll
                for (int i = 0; i < 4; i++) acc[mt][nt][i] = 0.0f;

#pragma unroll
        for (int kk = 0; kk < 8; kk++) {
            uint32_t b[2][4];
#pragma unroll
            for (int nh = 0; nh < 2; nh++)
                ldsm4t(b[nh], sB + (kk * 16 + lr) * BSTn + wn + nh * 16 + lc * 8);
            uint32_t a[2][4];
#pragma unroll
            for (int mt = 0; mt < 2; mt++)
                ldsm4(a[mt], sA + (wm + mt * 16 + lr) * AST + kk * 16 + lc * 8);
#pragma unroll
            for (int mt = 0; mt < 2; mt++)
#pragma unroll
                for (int nt = 0; nt < 4; nt++) {
                    int nh = nt >> 1, h = (nt & 1) * 2;
                    mma16816(acc[mt][nt], a[mt], b[nh][h], b[nh][h + 1]);
                }
        }

        bool isSelf = (n0 < out);
        __syncthreads();
#pragma unroll
        for (int mt = 0; mt < 2; mt++) {
#pragma unroll
            for (int nt = 0; nt < 4; nt++) {
                int scol = wn + nt * 8 + tg * 2;
                float b0 = 0.0f, b1 = 0.0f;
                if (isSelf) { b0 = bias[n0 + scol]; b1 = bias[n0 + scol + 1]; }
                int sr0 = wm + mt * 16 + g;
                *(__half2*)(sB + sr0 * BSTn + scol) =
                    __floats2half2_rn(acc[mt][nt][0] + b0, acc[mt][nt][1] + b1);
                *(__half2*)(sB + (sr0 + 8) * BSTn + scol) =
                    __floats2half2_rn(acc[mt][nt][2] + b0, acc[mt][nt][3] + b1);
            }
        }
        __syncthreads();
#pragma unroll
        for (int i = 0; i < 4; i++) {
            int idx = t + i * 128;
            int row = idx >> 3;
            int q8 = (idx & 7) * 8;
            int grow = m0 + row;
            if (grow < NN) {
                uint4 val = *(const uint4*)(sB + row * BSTn + q8);
                if (isSelf)
                    *(uint4*)(g_Ysh + (size_t)grow * out + n0 + q8) = val;
                else
                    *(uint4*)(g_Ym + (size_t)grow * pitchM + (n0 - out) + q8) = val;
            }
        }
    }
}

__global__ void __launch_bounds__(128, 6) k_gemm(const float* __restrict__ bias,
                                                 int out, int niter) {
    extern __shared__ __half smem[];
    gemm_body(bias, out, niter, blockIdx.x, smem);
}

// gemm0 + CSR fill fused: blocks [0,MG) gemm; [MG, MG+6*CNT_BLK_128) fill (128-thr granule)
#define FILL_BLK 6250   // EE / 128
__global__ void __launch_bounds__(128, 6) k_gemm0f(const float* __restrict__ bias,
                                                   const int* __restrict__ src,
                                                   const int* __restrict__ dst,
                                                   const int* __restrict__ ea) {
    extern __shared__ __half smem[];
    if (blockIdx.x < MG) {
        gemm_body(bias, 64, 5, blockIdx.x, smem);
    } else {
        int e = (blockIdx.x - MG) * 128 + threadIdx.x;
        if (e < EE) {
            int d = dst[e];
            int pos = atomicAdd(&g_fill[d], 1);
            g_csr[pos] = src[e] | (ea[e] << 28);
        }
    }
}

// ---------------- aggregation: one warp per node, 8-unrolled gather ----------------
#define AGG_BLK 6250
template <int OUT, int MODE, int QF, int NXT>
__global__ void __launch_bounds__(256) k_agg(float* __restrict__ Optr,
                                             const int* __restrict__ batch,
                                             const float* __restrict__ root,
                                             const float* __restrict__ W) {
    if (NXT > 0 && blockIdx.x >= AGG_BLK) {
        prepB_body((blockIdx.x - AGG_BLK) * 256 + threadIdx.x, root, W, NXT);
        return;
    }
    int w = (blockIdx.x * 256 + threadIdx.x) >> 5;
    if (w >= NN) return;
    int lane = threadIdx.x & 31;
    constexpr int V = OUT / 32;
    constexpr int PITCH = 4 * OUT;
    int start = g_rowptr[w], end = g_rowptr[w + 1];
    float4 iv4 = *(const float4*)(g_inv + w * 4);

    float acc[V];
    {
        const __half* sp = g_Ysh + (size_t)w * OUT + lane * V;
        if constexpr (V == 4) {
            uint2 s = *(const uint2*)sp;
            float2 s0 = __half22float2(*(__half2*)&s.x);
            float2 s1 = __half22float2(*(__half2*)&s.y);
            acc[0] = s0.x; acc[1] = s0.y; acc[2] = s1.x; acc[3] = s1.y;
        } else {
            uint32_t s = *(const uint32_t*)sp;
            float2 s0 = __half22float2(*(__half2*)&s);
            acc[0] = s0.x; acc[1] = s0.y;
        }
    }

    int e = start;
    for (; e + 8 <= end; e += 8) {
        int u[8];
#pragma unroll
        for (int j = 0; j < 8; j++) u[j] = g_csr[e + j];
        const __half* p[8];
        float iv[8];
#pragma unroll
        for (int j = 0; j < 8; j++) {
            int s = u[j] & 0x0FFFFFFF;
            int r = ((unsigned)u[j]) >> 28;
            p[j] = g_Ym + (size_t)s * PITCH + r * OUT + lane * V;
            iv[j] = pick4(iv4, r);
        }
        if constexpr (V == 4) {
            uint2 d[8];
#pragma unroll
            for (int j = 0; j < 8; j++) d[j] = *(const uint2*)p[j];
#pragma unroll
            for (int j = 0; j < 8; j++) {
                float2 m0 = __half22float2(*(__half2*)&d[j].x);
                float2 m1 = __half22float2(*(__half2*)&d[j].y);
                acc[0] += m0.x * iv[j]; acc[1] += m0.y * iv[j];
                acc[2] += m1.x * iv[j]; acc[3] += m1.y * iv[j];
            }
        } else {
            uint32_t d[8];
#pragma unroll
            for (int j = 0; j < 8; j++) d[j] = *(const uint32_t*)p[j];
#pragma unroll
            for (int j = 0; j < 8; j++) {
                float2 m0 = __half22float2(*(__half2*)&d[j]);
                acc[0] += m0.x * iv[j]; acc[1] += m0.y * iv[j];
            }
        }
    }
    for (; e < end; e++) {
        int u0 = g_csr[e];
        int s0 = u0 & 0x0FFFFFFF, r0 = ((unsigned)u0) >> 28;
        const __half* p0 = g_Ym + (size_t)s0 * PITCH + r0 * OUT + lane * V;
        float i0 = pick4(iv4, r0);
        if constexpr (V == 4) {
            uint2 w0 = *(const uint2*)p0;
            float2 a0 = __half22float2(*(__half2*)&w0.x);
            float2 a1 = __half22float2(*(__half2*)&w0.y);
            acc[0] += a0.x * i0; acc[1] += a0.y * i0;
            acc[2] += a1.x * i0; acc[3] += a1.y * i0;
        } else {
            uint32_t w0 = *(const uint32_t*)p0;
            float2 a0 = __half22float2(*(__half2*)&w0);
            acc[0] += a0.x * i0; acc[1] += a0.y * i0;
        }
    }

    if constexpr (MODE == 0) {
        union { __half h[V]; uint2 u2; uint32_t u1; } ph;
#pragma unroll
        for (int j = 0; j < V; j++)
            ph.h[j] = __float2half_rn(fmaxf(acc[j], 0.0f));
        __half* base = g_Asp + (size_t)w * 128 + lane * V;
        if constexpr (V == 4) *(uint2*)base = ph.u2;
        else                  *(uint32_t*)base = ph.u1;
        if constexpr (QF) {
            int b = batch[w];
            __half2 hh;
            hh.x = __float2half_rn(g_q[b * 64 + lane * 2]);
            hh.y = __float2half_rn(g_q[b * 64 + lane * 2 + 1]);
            *(__half2*)(g_Asp + (size_t)w * 128 + 64 + lane * 2) = hh;
        }
    } else {
        float* op = Optr + (size_t)w * OUT + lane * V;
        if constexpr (V == 4) {
            float4 r; r.x = acc[0]; r.y = acc[1]; r.z = acc[2]; r.w = acc[3];
            *(float4*)op = r;
        } else {
            float2 r; r.x = acc[0]; r.y = acc[1];
            *(float2*)op = r;
        }
    }
}

// ---------------- host orchestration ----------------
extern "C" void kernel_launch(void* const* d_in, const int* in_sizes, int n_in,
                              void* d_out, int out_size) {
    const float* x     = (const float*)d_in[0];
    const int*   ei    = (const int*)d_in[1];
    const int*   ea    = (const int*)d_in[2];
    const int*   batch = (const int*)d_in[3];
    const float* qe    = (const float*)d_in[4];
    const float* qnW   = (const float*)d_in[5];
    const float* qnb   = (const float*)d_in[6];
    const float* W0 = (const float*)d_in[7],  *root0 = (const float*)d_in[8],  *b0 = (const float*)d_in[9];
    const float* W1 = (const float*)d_in[10], *root1 = (const float*)d_in[11], *b1 = (const float*)d_in[12];
    const float* W2 = (const float*)d_in[13], *root2 = (const float*)d_in[14], *b2 = (const float*)d_in[15];
    const float* W3 = (const float*)d_in[16], *root3 = (const float*)d_in[17], *b3 = (const float*)d_in[18];
    float* out = (float*)d_out;

    const int* src = ei;
    const int* dst = ei + EE;

    cudaFuncSetAttribute(k_gemm, cudaFuncAttributeMaxDynamicSharedMemorySize, GEMM_SMEM);
    cudaFuncSetAttribute(k_gemm0f, cudaFuncAttributeMaxDynamicSharedMemorySize, GEMM_SMEM);

    // 1: fused prepA0(vec) + count + prepB0 + q
    k_mega1<<<PA_BLK + CNT_BLK + PB0_BLK + Q_BLK, 256>>>(x, dst, ea, root0, W0, qe, qnW, qnb);
    k_scan1<<<196, 256>>>();                                   // 2
    k_scan23<<<196, 256>>>();                                  // 3
    // 4: layer-0 GEMM + CSR fill, one heterogeneous launch (profiled)
    k_gemm0f<<<MG + FILL_BLK, 128, GEMM_SMEM>>>(b0, src, dst, ea);

    // 5: agg layer 0 (+q fill) + prepB1
    k_agg<64, 0, 1, 128><<<AGG_BLK + 320, 256>>>(nullptr, batch, root1, W1);
    // 6: layer 1
    k_gemm<<<MG, 128, GEMM_SMEM>>>(b1, 128, 10);
    // 7: agg layer 1 + prepB2
    k_agg<128, 0, 0, 128><<<AGG_BLK + 320, 256>>>(nullptr, nullptr, root2, W2);
    // 8: layer 2
    k_gemm<<<MG, 128, GEMM_SMEM>>>(b2, 128, 10);
    // 9: agg layer 2 + prepB3
    k_agg<128, 0, 0, 64><<<AGG_BLK + 160, 256>>>(nullptr, nullptr, root3, W3);
    // 10: layer 3
    k_gemm<<<MG, 128, GEMM_SMEM>>>(b3, 64, 5);
    // 11: final aggregation -> d_out
    k_agg<64, 1, 0, 0><<<AGG_BLK, 256>>>(out, nullptr, nullptr, nullptr);
}